// round 8
// baseline (speedup 1.0000x reference)
#include <cuda_runtime.h>
#include <cuda_bf16.h>
#include <math.h>

#define NTOK 4096
#define DDIM 1024
#define SDIM 16
#define NEXP 4
#define HDIM 2048
#define LSEQ 2048

// ---------------- scratch (static device globals; no allocation) ----------------
__device__ float g_delta[NTOK * DDIM];
__device__ float g_Bm[NTOK * SDIM];
__device__ float g_Cm[NTOK * SDIM];
__device__ float g_ssm[NTOK * DDIM];
__device__ float g_moe[NTOK * DDIM];
__device__ float g_G[NEXP * NTOK * HDIM];     // fp32 silu(xWg)*(xWu), per-expert slices
__device__ int   g_cnt[NEXP];
__device__ int   g_list[NEXP * NTOK];
__device__ float g_wgt[NEXP * NTOK];

// pre-converted bf16 hi/lo operands
__device__ __align__(16) __nv_bfloat16 g_x_h[NTOK * DDIM];
__device__ __align__(16) __nv_bfloat16 g_x_l[NTOK * DDIM];
__device__ __align__(16) __nv_bfloat16 g_ssm_h[NTOK * DDIM];
__device__ __align__(16) __nv_bfloat16 g_ssm_l[NTOK * DDIM];
__device__ __align__(16) __nv_bfloat16 g_G_h[NEXP * NTOK * HDIM];
__device__ __align__(16) __nv_bfloat16 g_G_l[NEXP * NTOK * HDIM];
__device__ __align__(16) __nv_bfloat16 g_Wdelta_h[DDIM * DDIM];
__device__ __align__(16) __nv_bfloat16 g_Wdelta_l[DDIM * DDIM];
__device__ __align__(16) __nv_bfloat16 g_Wg_h[NEXP * DDIM * HDIM];
__device__ __align__(16) __nv_bfloat16 g_Wg_l[NEXP * DDIM * HDIM];
__device__ __align__(16) __nv_bfloat16 g_Wu_h[NEXP * DDIM * HDIM];
__device__ __align__(16) __nv_bfloat16 g_Wu_l[NEXP * DDIM * HDIM];
__device__ __align__(16) __nv_bfloat16 g_Wdn_h[NEXP * HDIM * DDIM];
__device__ __align__(16) __nv_bfloat16 g_Wdn_l[NEXP * HDIM * DDIM];

// ---------------- helpers ----------------
__device__ __forceinline__ float softplusf(float z) {
    return fmaxf(z, 0.f) + log1pf(__expf(-fabsf(z)));
}
__device__ __forceinline__ float blockReduceSum(float v) {
    __shared__ float sh[9];
    int lane = threadIdx.x & 31, wid = threadIdx.x >> 5;
#pragma unroll
    for (int o = 16; o > 0; o >>= 1) v += __shfl_xor_sync(0xffffffffu, v, o);
    if (lane == 0) sh[wid] = v;
    __syncthreads();
    if (wid == 0) {
        float t = (lane < 8) ? sh[lane] : 0.f;
#pragma unroll
        for (int o = 4; o > 0; o >>= 1) t += __shfl_xor_sync(0xffffffffu, t, o);
        if (lane == 0) sh[8] = t;
    }
    __syncthreads();
    return sh[8];
}
__device__ __forceinline__ float bf16_rn(float v) {
    return __bfloat162float(__float2bfloat16(v));
}
__device__ __forceinline__ unsigned bf2(float e0, float e1) {  // e0 -> lower half
    unsigned r;
    asm("cvt.rn.bf16x2.f32 %0, %1, %2;" : "=r"(r) : "f"(e1), "f"(e0));
    return r;
}
__device__ __forceinline__ unsigned sptr(const void* p) {
    return (unsigned)__cvta_generic_to_shared(p);
}
__device__ __forceinline__ void ldmA(unsigned addr, unsigned& a0, unsigned& a1,
                                     unsigned& a2, unsigned& a3) {
    asm volatile("ldmatrix.sync.aligned.m8n8.x4.shared.b16 {%0,%1,%2,%3}, [%4];"
                 : "=r"(a0), "=r"(a1), "=r"(a2), "=r"(a3) : "r"(addr));
}
__device__ __forceinline__ void ldmB(unsigned addr, unsigned& b0, unsigned& b1) {
    asm volatile("ldmatrix.sync.aligned.m8n8.x2.trans.shared.b16 {%0,%1}, [%2];"
                 : "=r"(b0), "=r"(b1) : "r"(addr));
}
__device__ __forceinline__ void mma16816(float* c, const unsigned* a, unsigned b0, unsigned b1) {
    asm volatile("mma.sync.aligned.m16n8k16.row.col.f32.bf16.bf16.f32 "
                 "{%0,%1,%2,%3}, {%4,%5,%6,%7}, {%8,%9}, {%0,%1,%2,%3};"
                 : "+f"(c[0]), "+f"(c[1]), "+f"(c[2]), "+f"(c[3])
                 : "r"(a[0]), "r"(a[1]), "r"(a[2]), "r"(a[3]), "r"(b0), "r"(b1));
}

// ---------------- zero + convert ----------------
__global__ void k_zero() {
    int i = blockIdx.x * blockDim.x + threadIdx.x;
    int stride = gridDim.x * blockDim.x;
    for (int j = i; j < NTOK * DDIM; j += stride) g_moe[j] = 0.f;
    if (i < NEXP) g_cnt[i] = 0;
}

// fp32 -> (hi, lo) bf16 split, vectorized x4
__global__ void k_conv(const float4* __restrict__ src, uint2* __restrict__ h,
                       uint2* __restrict__ l, int n4) {
    int i = blockIdx.x * blockDim.x + threadIdx.x;
    int stride = gridDim.x * blockDim.x;
    for (; i < n4; i += stride) {
        float4 v = src[i];
        float h0 = bf16_rn(v.x), h1 = bf16_rn(v.y), h2 = bf16_rn(v.z), h3 = bf16_rn(v.w);
        uint2 hv, lv;
        hv.x = bf2(h0, h1); hv.y = bf2(h2, h3);
        lv.x = bf2(v.x - h0, v.y - h1); lv.y = bf2(v.z - h2, v.w - h3);
        h[i] = hv; l[i] = lv;
    }
}

// ============================================================================
// Pipelined bf16-split GEMM core. BM=128, BN=128, BK=32, 256 thr (8 warps 2x4),
// warp tile 64x32; 2-stage cp.async double buffer; operands pre-split hi/lo.
// D = Ah@Bh + Ah@Bl + Al@Bh (fp32 accumulate)
// ============================================================================
#define STAGE_U16 18944
#define AH_OFF 0
#define AL_OFF 5120
#define BH_OFF 10240
#define BL_OFF 14592
#define SMEM_BYTES (2 * STAGE_U16 * 2)

#define CPA(dst, src) \
    asm volatile("cp.async.ca.shared.global [%0], [%1], 16;" :: "r"(sptr(dst)), "l"(src))

#define GEMM_PRE                                                        \
    extern __shared__ __align__(16) unsigned short smem_u16[];          \
    int tid = threadIdx.x, lane = tid & 31, wrp = tid >> 5;             \
    int wm = wrp >> 2, wn = wrp & 3;                                    \
    int arow = tid >> 1, acol = (tid & 1) * 16;                         \
    int bkr = tid >> 3, bnc = (tid & 7) * 16;                           \
    float acc[4][4][4] = {};

#define GEMM_ISSUE(s, k0)                                                     \
    {                                                                         \
        unsigned short* _sb = smem_u16 + (s) * STAGE_U16;                     \
        CPA(_sb + AH_OFF + arow * 40 + acol,     aph + (k0) + acol);          \
        CPA(_sb + AH_OFF + arow * 40 + acol + 8, aph + (k0) + acol + 8);      \
        CPA(_sb + AL_OFF + arow * 40 + acol,     apl + (k0) + acol);          \
        CPA(_sb + AL_OFF + arow * 40 + acol + 8, apl + (k0) + acol + 8);      \
        const __nv_bfloat16* _bh = bph + (size_t)(k0) * NN;                   \
        const __nv_bfloat16* _bl = bpl + (size_t)(k0) * NN;                   \
        CPA(_sb + BH_OFF + bkr * 136 + bnc,     _bh + bnc);                   \
        CPA(_sb + BH_OFF + bkr * 136 + bnc + 8, _bh + bnc + 8);               \
        CPA(_sb + BL_OFF + bkr * 136 + bnc,     _bl + bnc);                   \
        CPA(_sb + BL_OFF + bkr * 136 + bnc + 8, _bl + bnc + 8);               \
        asm volatile("cp.async.commit_group;");                               \
    }

#define GEMM_COMPUTE(s)                                                       \
    {                                                                         \
        unsigned short* _sb = smem_u16 + (s) * STAGE_U16;                     \
        _Pragma("unroll")                                                     \
        for (int ks = 0; ks < 2; ks++) {                                      \
            unsigned ah[4][4], al[4][4], bh[4][2], bl[4][2];                  \
            int acol2 = ks * 16 + (lane >> 4) * 8;                            \
            int marow = wm * 64 + (lane & 15);                                \
            _Pragma("unroll")                                                 \
            for (int mb = 0; mb < 4; mb++) {                                  \
                ldmA(sptr(_sb + AH_OFF + (marow + mb * 16) * 40 + acol2),     \
                     ah[mb][0], ah[mb][1], ah[mb][2], ah[mb][3]);             \
                ldmA(sptr(_sb + AL_OFF + (marow + mb * 16) * 40 + acol2),     \
                     al[mb][0], al[mb][1], al[mb][2], al[mb][3]);             \
            }                                                                 \
            int bkrow = ks * 16 + (lane & 15);                                \
            _Pragma("unroll")                                                 \
            for (int nb = 0; nb < 4; nb++) {                                  \
                int nc = wn * 32 + nb * 8;                                    \
                ldmB(sptr(_sb + BH_OFF + bkrow * 136 + nc), bh[nb][0], bh[nb][1]); \
                ldmB(sptr(_sb + BL_OFF + bkrow * 136 + nc), bl[nb][0], bl[nb][1]); \
            }                                                                 \
            _Pragma("unroll")                                                 \
            for (int mb = 0; mb < 4; mb++)                                    \
                _Pragma("unroll")                                             \
                for (int nb = 0; nb < 4; nb++) {                              \
                    mma16816(acc[mb][nb], ah[mb], bh[nb][0], bh[nb][1]);      \
                    mma16816(acc[mb][nb], ah[mb], bl[nb][0], bl[nb][1]);      \
                    mma16816(acc[mb][nb], al[mb], bh[nb][0], bh[nb][1]);      \
                }                                                             \
        }                                                                     \
    }

#define GEMM_MAIN(NK)                                        \
    GEMM_ISSUE(0, 0)                                         \
    for (int i = 0; i < (NK); i++) {                         \
        if (i + 1 < (NK)) {                                  \
            GEMM_ISSUE((i + 1) & 1, (i + 1) * 32)            \
            asm volatile("cp.async.wait_group 1;");          \
        } else {                                             \
            asm volatile("cp.async.wait_group 0;");          \
        }                                                    \
        __syncthreads();                                     \
        GEMM_COMPUTE(i & 1)                                  \
        __syncthreads();                                     \
    }

// ---------------- delta GEMM: softplus(x @ W_delta + b) ----------------
__global__ void __launch_bounds__(256) k_delta(const float* __restrict__ bd) {
    GEMM_PRE
    const int NN = DDIM;
    int rowBase = blockIdx.x * 128, colBase = blockIdx.y * 128;
    const __nv_bfloat16* aph = g_x_h + (size_t)(rowBase + arow) * DDIM;
    const __nv_bfloat16* apl = g_x_l + (size_t)(rowBase + arow) * DDIM;
    const __nv_bfloat16* bph = g_Wdelta_h + (size_t)bkr * NN + colBase;
    const __nv_bfloat16* bpl = g_Wdelta_l + (size_t)bkr * NN + colBase;
    GEMM_MAIN(32)
    int g = lane >> 2, t = lane & 3;
#pragma unroll
    for (int mb = 0; mb < 4; mb++) {
        int r0 = rowBase + wm * 64 + mb * 16 + g;
#pragma unroll
        for (int nb = 0; nb < 4; nb++) {
            int c0 = colBase + wn * 32 + nb * 8 + t * 2;
            float b0 = bd[c0], b1 = bd[c0 + 1];
            g_delta[(size_t)r0 * NN + c0]           = softplusf(acc[mb][nb][0] + b0);
            g_delta[(size_t)r0 * NN + c0 + 1]       = softplusf(acc[mb][nb][1] + b1);
            g_delta[(size_t)(r0 + 8) * NN + c0]     = softplusf(acc[mb][nb][2] + b0);
            g_delta[(size_t)(r0 + 8) * NN + c0 + 1] = softplusf(acc[mb][nb][3] + b1);
        }
    }
}

// ---------------- gate GEMM (gathered, all experts): G = silu(X@Wg) ----------------
__global__ void __launch_bounds__(256) k_gate() {
    GEMM_PRE
    const int NN = HDIM;
    int e = blockIdx.z;
    int cnt = g_cnt[e];
    int rowBase = blockIdx.x * 128;
    if (rowBase >= cnt) return;
    int colBase = blockIdx.y * 128;
    int grow = rowBase + arow;
    int src = (grow < cnt) ? g_list[e * NTOK + grow] : g_list[e * NTOK];
    const __nv_bfloat16* aph = g_ssm_h + (size_t)src * DDIM;
    const __nv_bfloat16* apl = g_ssm_l + (size_t)src * DDIM;
    const __nv_bfloat16* bph = g_Wg_h + (size_t)e * DDIM * HDIM + (size_t)bkr * NN + colBase;
    const __nv_bfloat16* bpl = g_Wg_l + (size_t)e * DDIM * HDIM + (size_t)bkr * NN + colBase;
    GEMM_MAIN(32)
    int g = lane >> 2, t = lane & 3;
    float* Gout = g_G + (size_t)e * NTOK * HDIM;
#pragma unroll
    for (int mb = 0; mb < 4; mb++) {
        int r0 = rowBase + wm * 64 + mb * 16 + g;
#pragma unroll
        for (int nb = 0; nb < 4; nb++) {
            int c0 = colBase + wn * 32 + nb * 8 + t * 2;
            if (r0 < cnt) {
                float v0 = acc[mb][nb][0], v1 = acc[mb][nb][1];
                Gout[(size_t)r0 * NN + c0]     = v0 / (1.f + __expf(-v0));
                Gout[(size_t)r0 * NN + c0 + 1] = v1 / (1.f + __expf(-v1));
            }
            if (r0 + 8 < cnt) {
                float v2 = acc[mb][nb][2], v3 = acc[mb][nb][3];
                Gout[(size_t)(r0 + 8) * NN + c0]     = v2 / (1.f + __expf(-v2));
                Gout[(size_t)(r0 + 8) * NN + c0 + 1] = v3 / (1.f + __expf(-v3));
            }
        }
    }
}

// ---------------- up GEMM (gathered, all experts): G *= X@Wu ----------------
__global__ void __launch_bounds__(256) k_up() {
    GEMM_PRE
    const int NN = HDIM;
    int e = blockIdx.z;
    int cnt = g_cnt[e];
    int rowBase = blockIdx.x * 128;
    if (rowBase >= cnt) return;
    int colBase = blockIdx.y * 128;
    int grow = rowBase + arow;
    int src = (grow < cnt) ? g_list[e * NTOK + grow] : g_list[e * NTOK];
    const __nv_bfloat16* aph = g_ssm_h + (size_t)src * DDIM;
    const __nv_bfloat16* apl = g_ssm_l + (size_t)src * DDIM;
    const __nv_bfloat16* bph = g_Wu_h + (size_t)e * DDIM * HDIM + (size_t)bkr * NN + colBase;
    const __nv_bfloat16* bpl = g_Wu_l + (size_t)e * DDIM * HDIM + (size_t)bkr * NN + colBase;
    GEMM_MAIN(32)
    int g = lane >> 2, t = lane & 3;
    float* Gout = g_G + (size_t)e * NTOK * HDIM;
#pragma unroll
    for (int mb = 0; mb < 4; mb++) {
        int r0 = rowBase + wm * 64 + mb * 16 + g;
#pragma unroll
        for (int nb = 0; nb < 4; nb++) {
            int c0 = colBase + wn * 32 + nb * 8 + t * 2;
            if (r0 < cnt) {
                Gout[(size_t)r0 * NN + c0]     *= acc[mb][nb][0];
                Gout[(size_t)r0 * NN + c0 + 1] *= acc[mb][nb][1];
            }
            if (r0 + 8 < cnt) {
                Gout[(size_t)(r0 + 8) * NN + c0]     *= acc[mb][nb][2];
                Gout[(size_t)(r0 + 8) * NN + c0 + 1] *= acc[mb][nb][3];
            }
        }
    }
}

// ---------------- rmsnorm over expert hidden rows -> bf16 hi/lo ----------------
__global__ void k_rmsg(const float* __restrict__ wn) {
    int e = blockIdx.y;
    int m = blockIdx.x;
    if (m >= g_cnt[e]) return;
    size_t base = ((size_t)e * NTOK + m) * HDIM;
    const float* row = g_G + base;
    const float* w = wn + (size_t)e * HDIM;
    float v[8]; float ss = 0.f;
#pragma unroll
    for (int i = 0; i < 8; i++) {
        v[i] = row[threadIdx.x + i * 256];
        ss += v[i] * v[i];
    }
    ss = blockReduceSum(ss);
    float inv = 1.f / sqrtf(ss * (1.f / HDIM) + 1e-6f);
#pragma unroll
    for (int i = 0; i < 8; i++) {
        int j = threadIdx.x + i * 256;
        float val = w[j] * v[i] * inv;
        __nv_bfloat16 hh = __float2bfloat16(val);
        g_G_h[base + j] = hh;
        g_G_l[base + j] = __float2bfloat16(val - __bfloat162float(hh));
    }
}

// ---------------- down GEMM + weighted scatter-add (all experts, atomic) ----------------
__global__ void __launch_bounds__(256) k_down() {
    GEMM_PRE
    const int NN = DDIM;
    int e = blockIdx.z;
    int cnt = g_cnt[e];
    int rowBase = blockIdx.x * 128;
    if (rowBase >= cnt) return;
    int colBase = blockIdx.y * 128;
    const __nv_bfloat16* aph = g_G_h + ((size_t)e * NTOK + rowBase + arow) * HDIM;
    const __nv_bfloat16* apl = g_G_l + ((size_t)e * NTOK + rowBase + arow) * HDIM;
    const __nv_bfloat16* bph = g_Wdn_h + (size_t)e * HDIM * DDIM + (size_t)bkr * NN + colBase;
    const __nv_bfloat16* bpl = g_Wdn_l + (size_t)e * HDIM * DDIM + (size_t)bkr * NN + colBase;
    GEMM_MAIN(64)
    int g = lane >> 2, t = lane & 3;
#pragma unroll
    for (int mb = 0; mb < 4; mb++) {
        int r0 = rowBase + wm * 64 + mb * 16 + g;
#pragma unroll
        for (int nb = 0; nb < 4; nb++) {
            int c0 = colBase + wn * 32 + nb * 8 + t * 2;
            // atomicAdd: each g_moe element receives exactly 2 expert contributions
            // (fp add is commutative -> bit-deterministic regardless of order)
            if (r0 < cnt) {
                int tok = g_list[e * NTOK + r0];
                float w = g_wgt[e * NTOK + r0];
                atomicAdd(&g_moe[(size_t)tok * NN + c0],     w * acc[mb][nb][0]);
                atomicAdd(&g_moe[(size_t)tok * NN + c0 + 1], w * acc[mb][nb][1]);
            }
            if (r0 + 8 < cnt) {
                int tok = g_list[e * NTOK + r0 + 8];
                float w = g_wgt[e * NTOK + r0 + 8];
                atomicAdd(&g_moe[(size_t)tok * NN + c0],     w * acc[mb][nb][2]);
                atomicAdd(&g_moe[(size_t)tok * NN + c0 + 1], w * acc[mb][nb][3]);
            }
        }
    }
}

// ---------------- Bm / Cm: skinny GEMM, one warp per token ----------------
__global__ void k_bc(const float* __restrict__ x, const float* __restrict__ WB,
                     const float* __restrict__ WC) {
    int wid = (blockIdx.x * blockDim.x + threadIdx.x) >> 5;
    int lane = threadIdx.x & 31;
    if (wid >= NTOK) return;
    const float* W = (lane < 16) ? WB : WC;
    int col = lane & 15;
    const float* xr = x + (size_t)wid * DDIM;
    float acc = 0.f;
#pragma unroll 8
    for (int k = 0; k < DDIM; k++) acc = fmaf(xr[k], W[k * SDIM + col], acc);
    if (lane < 16) g_Bm[wid * SDIM + col] = acc;
    else           g_Cm[wid * SDIM + col] = acc;
}

// ---------------- selective scan + ssm hi/lo epilogue ----------------
__global__ void k_scan(const float* __restrict__ x, const float* __restrict__ A_log,
                       const float* __restrict__ Dp) {
    int tid = threadIdx.x;
    int grp = tid >> 4, s = tid & 15;
    int c = blockIdx.x * 16 + grp;
    int b = c >> 10, d = c & 1023;
    float a = -__expf(A_log[d * SDIM + s]);
    float dpar = Dp[d];
    float h = 0.f;
    const float* xb = x + (size_t)b * LSEQ * DDIM + d;
    const float* db = g_delta + (size_t)b * LSEQ * DDIM + d;
    const float* Bb = g_Bm + (size_t)b * LSEQ * SDIM + s;
    const float* Cb = g_Cm + (size_t)b * LSEQ * SDIM + s;
    size_t ybase = (size_t)b * LSEQ * DDIM + d;
#pragma unroll 4
    for (int t = 0; t < LSEQ; t++) {
        float dv = db[(size_t)t * DDIM];
        float xv = xb[(size_t)t * DDIM];
        float Bv = Bb[t * SDIM];
        float Cv = Cb[t * SDIM];
        float barA = __expf(fminf(dv * a, 10.f));
        float barB = fminf(fmaxf(dv * Bv, -10.f), 10.f);
        h = fminf(fmaxf(fmaf(barA, h, barB * xv), -10000.f), 10000.f);
        float p = h * Cv;
        p += __shfl_xor_sync(0xffffffffu, p, 8);
        p += __shfl_xor_sync(0xffffffffu, p, 4);
        p += __shfl_xor_sync(0xffffffffu, p, 2);
        p += __shfl_xor_sync(0xffffffffu, p, 1);
        if (s == 0) {
            float y = p + xv * dpar;
            size_t idx = ybase + (size_t)t * DDIM;
            g_ssm[idx] = y;
            __nv_bfloat16 hh = __float2bfloat16(y);
            g_ssm_h[idx] = hh;
            g_ssm_l[idx] = __float2bfloat16(y - __bfloat162float(hh));
        }
    }
}

// ---------------- router: softmax over E=4, top-2, build per-expert lists ----------------
__global__ void k_router(const float* __restrict__ Wr) {
    int wid = (blockIdx.x * blockDim.x + threadIdx.x) >> 5;
    int lane = threadIdx.x & 31;
    if (wid >= NTOK) return;
    const float* xr = g_ssm + (size_t)wid * DDIM;
    float l[4] = {0.f, 0.f, 0.f, 0.f};
    for (int k = lane; k < DDIM; k += 32) {
        float xv = xr[k];
        float4 w = *(const float4*)(Wr + (size_t)k * 4);
        l[0] = fmaf(xv, w.x, l[0]);
        l[1] = fmaf(xv, w.y, l[1]);
        l[2] = fmaf(xv, w.z, l[2]);
        l[3] = fmaf(xv, w.w, l[3]);
    }
#pragma unroll
    for (int e = 0; e < 4; e++)
#pragma unroll
        for (int o = 16; o > 0; o >>= 1) l[e] += __shfl_xor_sync(0xffffffffu, l[e], o);
    if (lane == 0) {
        float m = fmaxf(fmaxf(l[0], l[1]), fmaxf(l[2], l[3]));
        float p[4]; float ssum = 0.f;
#pragma unroll
        for (int e = 0; e < 4; e++) { p[e] = __expf(l[e] - m); ssum += p[e]; }
#pragma unroll
        for (int e = 0; e < 4; e++) p[e] /= ssum;
        int e1 = 0; float b1 = p[0];
#pragma unroll
        for (int e = 1; e < 4; e++) if (p[e] > b1) { b1 = p[e]; e1 = e; }
        int e2 = -1; float b2 = -1.f;
#pragma unroll
        for (int e = 0; e < 4; e++) if (e != e1 && p[e] > b2) { b2 = p[e]; e2 = e; }
        float wsum = b1 + b2 + 1e-9f;
        float w1 = b1 / wsum, w2 = b2 / wsum;
        int pos1 = atomicAdd(&g_cnt[e1], 1);
        g_list[e1 * NTOK + pos1] = wid; g_wgt[e1 * NTOK + pos1] = w1;
        int pos2 = atomicAdd(&g_cnt[e2], 1);
        g_list[e2 * NTOK + pos2] = wid; g_wgt[e2 * NTOK + pos2] = w2;
    }
}

// ---------------- final rmsnorm(ssm + moe) ----------------
__global__ void k_final(const float* __restrict__ nw, float* __restrict__ out) {
    int n = blockIdx.x;
    int t = threadIdx.x;
    float v[4]; float ss = 0.f;
#pragma unroll
    for (int i = 0; i < 4; i++) {
        int j = t + i * 256;
        v[i] = g_ssm[(size_t)n * DDIM + j] + g_moe[(size_t)n * DDIM + j];
        ss += v[i] * v[i];
    }
    ss = blockReduceSum(ss);
    float inv = 1.f / sqrtf(ss * (1.f / DDIM) + 1e-6f);
#pragma unroll
    for (int i = 0; i < 4; i++) {
        int j = t + i * 256;
        out[(size_t)n * DDIM + j] = nw[j] * v[i] * inv;
    }
}

// ---------------- launch ----------------
extern "C" void kernel_launch(void* const* d_in, const int* in_sizes, int n_in,
                              void* d_out, int out_size) {
    (void)in_sizes; (void)n_in; (void)out_size;
    const float* x        = (const float*)d_in[0];
    const float* A_log    = (const float*)d_in[1];
    const float* D_param  = (const float*)d_in[2];
    const float* W_delta  = (const float*)d_in[3];
    const float* b_delta  = (const float*)d_in[4];
    const float* W_B      = (const float*)d_in[5];
    const float* W_C      = (const float*)d_in[6];
    const float* W_router = (const float*)d_in[7];
    const float* Wg       = (const float*)d_in[8];
    const float* Wu       = (const float*)d_in[9];
    const float* Wd       = (const float*)d_in[10];
    const float* wn_exp   = (const float*)d_in[11];
    const float* norm_w   = (const float*)d_in[12];
    float* out = (float*)d_out;

    cudaFuncSetAttribute(k_delta, cudaFuncAttributeMaxDynamicSharedMemorySize, SMEM_BYTES);
    cudaFuncSetAttribute(k_gate,  cudaFuncAttributeMaxDynamicSharedMemorySize, SMEM_BYTES);
    cudaFuncSetAttribute(k_up,    cudaFuncAttributeMaxDynamicSharedMemorySize, SMEM_BYTES);
    cudaFuncSetAttribute(k_down,  cudaFuncAttributeMaxDynamicSharedMemorySize, SMEM_BYTES);

    // device-pointer helpers for the converted buffers
    __nv_bfloat16 *xh, *xl, *wdh, *wdl, *wgh, *wgl, *wuh, *wul, *wnh, *wnl;
    cudaGetSymbolAddress((void**)&xh,  g_x_h);
    cudaGetSymbolAddress((void**)&xl,  g_x_l);
    cudaGetSymbolAddress((void**)&wdh, g_Wdelta_h);
    cudaGetSymbolAddress((void**)&wdl, g_Wdelta_l);
    cudaGetSymbolAddress((void**)&wgh, g_Wg_h);
    cudaGetSymbolAddress((void**)&wgl, g_Wg_l);
    cudaGetSymbolAddress((void**)&wuh, g_Wu_h);
    cudaGetSymbolAddress((void**)&wul, g_Wu_l);
    cudaGetSymbolAddress((void**)&wnh, g_Wdn_h);
    cudaGetSymbolAddress((void**)&wnl, g_Wdn_l);

    k_zero<<<1024, 256>>>();
    k_conv<<<1024, 256>>>((const float4*)x,       (uint2*)xh,  (uint2*)xl,  NTOK * DDIM / 4);
    k_conv<<<1024, 256>>>((const float4*)W_delta, (uint2*)wdh, (uint2*)wdl, DDIM * DDIM / 4);
    k_conv<<<2048, 256>>>((const float4*)Wg,      (uint2*)wgh, (uint2*)wgl, NEXP * DDIM * HDIM / 4);
    k_conv<<<2048, 256>>>((const float4*)Wu,      (uint2*)wuh, (uint2*)wul, NEXP * DDIM * HDIM / 4);
    k_conv<<<2048, 256>>>((const float4*)Wd,      (uint2*)wnh, (uint2*)wnl, NEXP * HDIM * DDIM / 4);

    k_delta<<<dim3(32, 8), 256, SMEM_BYTES>>>(b_delta);
    k_bc<<<512, 256>>>(x, W_B, W_C);
    k_scan<<<128, 256>>>(x, A_log, D_param);
    k_router<<<512, 256>>>(W_router);

    k_gate<<<dim3(32, 16, NEXP), 256, SMEM_BYTES>>>();
    k_up<<<dim3(32, 16, NEXP), 256, SMEM_BYTES>>>();
    k_rmsg<<<dim3(NTOK, NEXP), 256>>>(wn_exp);
    k_down<<<dim3(32, 8, NEXP), 256, SMEM_BYTES>>>();

    k_final<<<4096, 256>>>(norm_w, out);
}

// round 14
// speedup vs baseline: 1.2897x; 1.2897x over previous
#include <cuda_runtime.h>
#include <cuda_bf16.h>
#include <math.h>

#define NTOK 4096
#define DDIM 1024
#define SDIM 16
#define NEXP 4
#define HDIM 2048
#define LSEQ 2048

// ---------------- scratch (static device globals; no allocation) ----------------
__device__ float g_delta[NTOK * DDIM];
__device__ float g_Bm[NTOK * SDIM];
__device__ float g_Cm[NTOK * SDIM];
__device__ float g_ssm[NTOK * DDIM];
__device__ float g_moe[NTOK * DDIM];
__device__ float g_G[NEXP * NTOK * HDIM];   // fp32 per-expert hidden
__device__ int   g_cnt[NEXP];
__device__ int   g_list[NEXP * NTOK];
__device__ float g_wgt[NEXP * NTOK];

// pre-split bf16 hi/lo operands (same layouts as fp32 sources)
__device__ __align__(16) __nv_bfloat16 g_x_h[NTOK * DDIM];
__device__ __align__(16) __nv_bfloat16 g_x_l[NTOK * DDIM];
__device__ __align__(16) __nv_bfloat16 g_ssm_h[NTOK * DDIM];
__device__ __align__(16) __nv_bfloat16 g_ssm_l[NTOK * DDIM];
__device__ __align__(16) __nv_bfloat16 g_G_h[NEXP * NTOK * HDIM];
__device__ __align__(16) __nv_bfloat16 g_G_l[NEXP * NTOK * HDIM];
__device__ __align__(16) __nv_bfloat16 g_Wde_h[DDIM * DDIM];
__device__ __align__(16) __nv_bfloat16 g_Wde_l[DDIM * DDIM];
__device__ __align__(16) __nv_bfloat16 g_Wg_h[NEXP * DDIM * HDIM];
__device__ __align__(16) __nv_bfloat16 g_Wg_l[NEXP * DDIM * HDIM];
__device__ __align__(16) __nv_bfloat16 g_Wu_h[NEXP * DDIM * HDIM];
__device__ __align__(16) __nv_bfloat16 g_Wu_l[NEXP * DDIM * HDIM];
__device__ __align__(16) __nv_bfloat16 g_Wdn_h[NEXP * HDIM * DDIM];
__device__ __align__(16) __nv_bfloat16 g_Wdn_l[NEXP * HDIM * DDIM];

// ---------------- helpers ----------------
__device__ __forceinline__ float softplusf(float z) {
    return fmaxf(z, 0.f) + log1pf(__expf(-fabsf(z)));
}
__device__ __forceinline__ float blockReduceSum(float v) {
    __shared__ float sh[9];
    int lane = threadIdx.x & 31, wid = threadIdx.x >> 5;
#pragma unroll
    for (int o = 16; o > 0; o >>= 1) v += __shfl_xor_sync(0xffffffffu, v, o);
    if (lane == 0) sh[wid] = v;
    __syncthreads();
    if (wid == 0) {
        float t = (lane < 8) ? sh[lane] : 0.f;
#pragma unroll
        for (int o = 4; o > 0; o >>= 1) t += __shfl_xor_sync(0xffffffffu, t, o);
        if (lane == 0) sh[8] = t;
    }
    __syncthreads();
    return sh[8];
}
__device__ __forceinline__ unsigned sptr(const void* p) {
    return (unsigned)__cvta_generic_to_shared(p);
}
__device__ __forceinline__ void ldmA(unsigned addr, unsigned& a0, unsigned& a1,
                                     unsigned& a2, unsigned& a3) {
    asm volatile("ldmatrix.sync.aligned.m8n8.x4.shared.b16 {%0,%1,%2,%3}, [%4];"
                 : "=r"(a0), "=r"(a1), "=r"(a2), "=r"(a3) : "r"(addr));
}
__device__ __forceinline__ void ldmB(unsigned addr, unsigned& b0, unsigned& b1) {
    asm volatile("ldmatrix.sync.aligned.m8n8.x2.trans.shared.b16 {%0,%1}, [%2];"
                 : "=r"(b0), "=r"(b1) : "r"(addr));
}
__device__ __forceinline__ void mma16816(float* c, const unsigned* a, unsigned b0, unsigned b1) {
    asm volatile("mma.sync.aligned.m16n8k16.row.col.f32.bf16.bf16.f32 "
                 "{%0,%1,%2,%3}, {%4,%5,%6,%7}, {%8,%9}, {%0,%1,%2,%3};"
                 : "+f"(c[0]), "+f"(c[1]), "+f"(c[2]), "+f"(c[3])
                 : "r"(a[0]), "r"(a[1]), "r"(a[2]), "r"(a[3]), "r"(b0), "r"(b1));
}
#define CPA(dst, src) \
    asm volatile("cp.async.ca.shared.global [%0], [%1], 16;" :: "r"(sptr(dst)), "l"(src))

// ---------------- zero + split-convert ----------------
__global__ void k_zero() {
    int i = blockIdx.x * blockDim.x + threadIdx.x;
    int stride = gridDim.x * blockDim.x;
    for (int j = i; j < NTOK * DDIM; j += stride) g_moe[j] = 0.f;
    if (i < NEXP) g_cnt[i] = 0;
}

__global__ void k_conv(const float4* __restrict__ src, uint2* __restrict__ h,
                       uint2* __restrict__ l, int n4) {
    int i = blockIdx.x * blockDim.x + threadIdx.x;
    int stride = gridDim.x * blockDim.x;
    for (; i < n4; i += stride) {
        float4 v = src[i];
        __nv_bfloat16 h0 = __float2bfloat16(v.x), h1 = __float2bfloat16(v.y);
        __nv_bfloat16 h2 = __float2bfloat16(v.z), h3 = __float2bfloat16(v.w);
        __nv_bfloat16 l0 = __float2bfloat16(v.x - __bfloat162float(h0));
        __nv_bfloat16 l1 = __float2bfloat16(v.y - __bfloat162float(h1));
        __nv_bfloat16 l2 = __float2bfloat16(v.z - __bfloat162float(h2));
        __nv_bfloat16 l3 = __float2bfloat16(v.w - __bfloat162float(h3));
        uint2 hv, lv;
        hv.x = ((unsigned)__bfloat16_as_ushort(h1) << 16) | __bfloat16_as_ushort(h0);
        hv.y = ((unsigned)__bfloat16_as_ushort(h3) << 16) | __bfloat16_as_ushort(h2);
        lv.x = ((unsigned)__bfloat16_as_ushort(l1) << 16) | __bfloat16_as_ushort(l0);
        lv.y = ((unsigned)__bfloat16_as_ushort(l3) << 16) | __bfloat16_as_ushort(l2);
        h[i] = hv; l[i] = lv;
    }
}

// ============================================================================
// bf16-split GEMM core (R5 structure, pre-split operands, cp.async loads).
// BM=128, BN=128, BK=32, 256 threads (8 warps 2x4), warp tile 64x32.
// Single-buffer smem (~37.9KB) -> 2 CTAs/SM for cross-CTA overlap.
// D = Ah@Bh + Ah@Bl + Al@Bh (fp32 accumulate)
// ============================================================================
#define GEMM_SMEM                                            \
    __shared__ __align__(16) unsigned short Ah[128][40];     \
    __shared__ __align__(16) unsigned short Al[128][40];     \
    __shared__ __align__(16) unsigned short Bh[32][136];     \
    __shared__ __align__(16) unsigned short Bl[32][136];

#define GEMM_PRE                                                        \
    int tid = threadIdx.x, lane = tid & 31, wrp = tid >> 5;             \
    int wm = wrp >> 2, wn = wrp & 3;                                    \
    int arow = tid >> 1, akb = (tid & 1) * 16;                          \
    int bkr = tid >> 3, bnc = (tid & 7) * 16;                           \
    float acc[4][4][4] = {};

#define GEMM_LOAD(k0)                                                   \
    {                                                                   \
        CPA(&Ah[arow][akb],     aph + (k0) + akb);                      \
        CPA(&Ah[arow][akb + 8], aph + (k0) + akb + 8);                  \
        CPA(&Al[arow][akb],     apl + (k0) + akb);                      \
        CPA(&Al[arow][akb + 8], apl + (k0) + akb + 8);                  \
        const __nv_bfloat16* _bh = bph + (size_t)(k0) * NN;             \
        const __nv_bfloat16* _bl = bpl + (size_t)(k0) * NN;             \
        CPA(&Bh[bkr][bnc],     _bh + bnc);                              \
        CPA(&Bh[bkr][bnc + 8], _bh + bnc + 8);                          \
        CPA(&Bl[bkr][bnc],     _bl + bnc);                              \
        CPA(&Bl[bkr][bnc + 8], _bl + bnc + 8);                          \
        asm volatile("cp.async.commit_group;");                         \
        asm volatile("cp.async.wait_group 0;");                         \
        __syncthreads();                                                \
    }

#define GEMM_COMPUTE                                                          \
    _Pragma("unroll")                                                         \
    for (int ks = 0; ks < 2; ks++) {                                          \
        unsigned ah[4][4], al[4][4], bh[4][2], bl[4][2];                      \
        int acol2 = ks * 16 + (lane >> 4) * 8;                                \
        int marow = wm * 64 + (lane & 15);                                    \
        _Pragma("unroll")                                                     \
        for (int mb = 0; mb < 4; mb++) {                                      \
            ldmA(sptr(&Ah[marow + mb * 16][acol2]),                           \
                 ah[mb][0], ah[mb][1], ah[mb][2], ah[mb][3]);                 \
            ldmA(sptr(&Al[marow + mb * 16][acol2]),                           \
                 al[mb][0], al[mb][1], al[mb][2], al[mb][3]);                 \
        }                                                                     \
        int bkrow = ks * 16 + (lane & 15);                                    \
        _Pragma("unroll")                                                     \
        for (int nb = 0; nb < 4; nb++) {                                      \
            int nc = wn * 32 + nb * 8;                                        \
            ldmB(sptr(&Bh[bkrow][nc]), bh[nb][0], bh[nb][1]);                 \
            ldmB(sptr(&Bl[bkrow][nc]), bl[nb][0], bl[nb][1]);                 \
        }                                                                     \
        _Pragma("unroll")                                                     \
        for (int mb = 0; mb < 4; mb++)                                        \
            _Pragma("unroll")                                                 \
            for (int nb = 0; nb < 4; nb++) {                                  \
                mma16816(acc[mb][nb], ah[mb], bh[nb][0], bh[nb][1]);          \
                mma16816(acc[mb][nb], ah[mb], bl[nb][0], bl[nb][1]);          \
                mma16816(acc[mb][nb], al[mb], bh[nb][0], bh[nb][1]);          \
            }                                                                 \
    }

#define GEMM_MAIN(KTOT)                       \
    for (int k0 = 0; k0 < (KTOT); k0 += 32) { \
        GEMM_LOAD(k0)                         \
        GEMM_COMPUTE                          \
        __syncthreads();                      \
    }

// ---------------- delta GEMM: softplus(x @ W_delta + b) ----------------
__global__ void __launch_bounds__(256) k_delta(const float* __restrict__ bd) {
    GEMM_SMEM
    GEMM_PRE
    const int NN = DDIM;
    int rowBase = blockIdx.x * 128, colBase = blockIdx.y * 128;
    const __nv_bfloat16* aph = g_x_h + (size_t)(rowBase + arow) * DDIM;
    const __nv_bfloat16* apl = g_x_l + (size_t)(rowBase + arow) * DDIM;
    const __nv_bfloat16* bph = g_Wde_h + (size_t)bkr * NN + colBase + 0;
    const __nv_bfloat16* bpl = g_Wde_l + (size_t)bkr * NN + colBase + 0;
    GEMM_MAIN(DDIM)
    int g = lane >> 2, t = lane & 3;
#pragma unroll
    for (int mb = 0; mb < 4; mb++) {
        int r0 = rowBase + wm * 64 + mb * 16 + g;
#pragma unroll
        for (int nb = 0; nb < 4; nb++) {
            int c0 = colBase + wn * 32 + nb * 8 + t * 2;
            float b0 = bd[c0], b1 = bd[c0 + 1];
            g_delta[(size_t)r0 * NN + c0]           = softplusf(acc[mb][nb][0] + b0);
            g_delta[(size_t)r0 * NN + c0 + 1]       = softplusf(acc[mb][nb][1] + b1);
            g_delta[(size_t)(r0 + 8) * NN + c0]     = softplusf(acc[mb][nb][2] + b0);
            g_delta[(size_t)(r0 + 8) * NN + c0 + 1] = softplusf(acc[mb][nb][3] + b1);
        }
    }
}

// ---------------- gate GEMM (gathered, batched experts): G = silu(X@Wg) ----------------
__global__ void __launch_bounds__(256) k_gate() {
    GEMM_SMEM
    GEMM_PRE
    const int NN = HDIM;
    int e = blockIdx.z;
    int cnt = g_cnt[e];
    int rowBase = blockIdx.x * 128;
    if (rowBase >= cnt) return;
    int colBase = blockIdx.y * 128;
    int grow = rowBase + arow;
    int src = (grow < cnt) ? g_list[e * NTOK + grow] : g_list[e * NTOK];
    const __nv_bfloat16* aph = g_ssm_h + (size_t)src * DDIM;
    const __nv_bfloat16* apl = g_ssm_l + (size_t)src * DDIM;
    const __nv_bfloat16* bph = g_Wg_h + (size_t)e * DDIM * HDIM + (size_t)bkr * NN + colBase;
    const __nv_bfloat16* bpl = g_Wg_l + (size_t)e * DDIM * HDIM + (size_t)bkr * NN + colBase;
    GEMM_MAIN(DDIM)
    int g = lane >> 2, t = lane & 3;
    float* Gout = g_G + (size_t)e * NTOK * HDIM;
#pragma unroll
    for (int mb = 0; mb < 4; mb++) {
        int r0 = rowBase + wm * 64 + mb * 16 + g;
#pragma unroll
        for (int nb = 0; nb < 4; nb++) {
            int c0 = colBase + wn * 32 + nb * 8 + t * 2;
            if (r0 < cnt) {
                float v0 = acc[mb][nb][0], v1 = acc[mb][nb][1];
                Gout[(size_t)r0 * NN + c0]     = v0 / (1.f + __expf(-v0));
                Gout[(size_t)r0 * NN + c0 + 1] = v1 / (1.f + __expf(-v1));
            }
            if (r0 + 8 < cnt) {
                float v2 = acc[mb][nb][2], v3 = acc[mb][nb][3];
                Gout[(size_t)(r0 + 8) * NN + c0]     = v2 / (1.f + __expf(-v2));
                Gout[(size_t)(r0 + 8) * NN + c0 + 1] = v3 / (1.f + __expf(-v3));
            }
        }
    }
}

// ---------------- up GEMM (gathered, batched experts): G *= X@Wu ----------------
__global__ void __launch_bounds__(256) k_up() {
    GEMM_SMEM
    GEMM_PRE
    const int NN = HDIM;
    int e = blockIdx.z;
    int cnt = g_cnt[e];
    int rowBase = blockIdx.x * 128;
    if (rowBase >= cnt) return;
    int colBase = blockIdx.y * 128;
    int grow = rowBase + arow;
    int src = (grow < cnt) ? g_list[e * NTOK + grow] : g_list[e * NTOK];
    const __nv_bfloat16* aph = g_ssm_h + (size_t)src * DDIM;
    const __nv_bfloat16* apl = g_ssm_l + (size_t)src * DDIM;
    const __nv_bfloat16* bph = g_Wu_h + (size_t)e * DDIM * HDIM + (size_t)bkr * NN + colBase;
    const __nv_bfloat16* bpl = g_Wu_l + (size_t)e * DDIM * HDIM + (size_t)bkr * NN + colBase;
    GEMM_MAIN(DDIM)
    int g = lane >> 2, t = lane & 3;
    float* Gout = g_G + (size_t)e * NTOK * HDIM;
#pragma unroll
    for (int mb = 0; mb < 4; mb++) {
        int r0 = rowBase + wm * 64 + mb * 16 + g;
#pragma unroll
        for (int nb = 0; nb < 4; nb++) {
            int c0 = colBase + wn * 32 + nb * 8 + t * 2;
            if (r0 < cnt) {
                Gout[(size_t)r0 * NN + c0]     *= acc[mb][nb][0];
                Gout[(size_t)r0 * NN + c0 + 1] *= acc[mb][nb][1];
            }
            if (r0 + 8 < cnt) {
                Gout[(size_t)(r0 + 8) * NN + c0]     *= acc[mb][nb][2];
                Gout[(size_t)(r0 + 8) * NN + c0 + 1] *= acc[mb][nb][3];
            }
        }
    }
}

// ---------------- rmsnorm over expert hidden rows -> bf16 hi/lo ----------------
__global__ void k_rmsg(const float* __restrict__ wn) {
    int e = blockIdx.y;
    int m = blockIdx.x;
    if (m >= g_cnt[e]) return;
    size_t base = ((size_t)e * NTOK + m) * HDIM;
    const float* row = g_G + base;
    const float* w = wn + (size_t)e * HDIM;
    float v[8]; float ss = 0.f;
#pragma unroll
    for (int i = 0; i < 8; i++) {
        v[i] = row[threadIdx.x + i * 256];
        ss += v[i] * v[i];
    }
    ss = blockReduceSum(ss);
    float inv = 1.f / sqrtf(ss * (1.f / HDIM) + 1e-6f);
#pragma unroll
    for (int i = 0; i < 8; i++) {
        int j = threadIdx.x + i * 256;
        float val = w[j] * v[i] * inv;
        __nv_bfloat16 hh = __float2bfloat16(val);
        g_G_h[base + j] = hh;
        g_G_l[base + j] = __float2bfloat16(val - __bfloat162float(hh));
    }
}

// ---------------- down GEMM + weighted atomic scatter (batched experts) ----------------
__global__ void __launch_bounds__(256) k_down() {
    GEMM_SMEM
    GEMM_PRE
    const int NN = DDIM;
    int e = blockIdx.z;
    int cnt = g_cnt[e];
    int rowBase = blockIdx.x * 128;
    if (rowBase >= cnt) return;
    int colBase = blockIdx.y * 128;
    int grow = rowBase + arow;
    int ar2 = (grow < cnt) ? grow : (cnt - 1);
    const __nv_bfloat16* aph = g_G_h + ((size_t)e * NTOK + ar2) * HDIM;
    const __nv_bfloat16* apl = g_G_l + ((size_t)e * NTOK + ar2) * HDIM;
    const __nv_bfloat16* bph = g_Wdn_h + (size_t)e * HDIM * DDIM + (size_t)bkr * NN + colBase;
    const __nv_bfloat16* bpl = g_Wdn_l + (size_t)e * HDIM * DDIM + (size_t)bkr * NN + colBase;
    GEMM_MAIN(HDIM)
    int g = lane >> 2, t = lane & 3;
#pragma unroll
    for (int mb = 0; mb < 4; mb++) {
        int r0 = rowBase + wm * 64 + mb * 16 + g;
#pragma unroll
        for (int nb = 0; nb < 4; nb++) {
            int c0 = colBase + wn * 32 + nb * 8 + t * 2;
            if (r0 < cnt) {
                int tok = g_list[e * NTOK + r0];
                float w = g_wgt[e * NTOK + r0];
                atomicAdd(&g_moe[(size_t)tok * NN + c0],     w * acc[mb][nb][0]);
                atomicAdd(&g_moe[(size_t)tok * NN + c0 + 1], w * acc[mb][nb][1]);
            }
            if (r0 + 8 < cnt) {
                int tok = g_list[e * NTOK + r0 + 8];
                float w = g_wgt[e * NTOK + r0 + 8];
                atomicAdd(&g_moe[(size_t)tok * NN + c0],     w * acc[mb][nb][2]);
                atomicAdd(&g_moe[(size_t)tok * NN + c0 + 1], w * acc[mb][nb][3]);
            }
        }
    }
}

// ---------------- Bm / Cm ----------------
__global__ void k_bc(const float* __restrict__ x, const float* __restrict__ WB,
                     const float* __restrict__ WC) {
    int wid = (blockIdx.x * blockDim.x + threadIdx.x) >> 5;
    int lane = threadIdx.x & 31;
    if (wid >= NTOK) return;
    const float* W = (lane < 16) ? WB : WC;
    int col = lane & 15;
    const float* xr = x + (size_t)wid * DDIM;
    float acc = 0.f;
#pragma unroll 8
    for (int k = 0; k < DDIM; k++) acc = fmaf(xr[k], W[k * SDIM + col], acc);
    if (lane < 16) g_Bm[wid * SDIM + col] = acc;
    else           g_Cm[wid * SDIM + col] = acc;
}

// ---------------- selective scan + ssm hi/lo epilogue ----------------
__global__ void k_scan(const float* __restrict__ x, const float* __restrict__ A_log,
                       const float* __restrict__ Dp) {
    int tid = threadIdx.x;
    int grp = tid >> 4, s = tid & 15;
    int c = blockIdx.x * 16 + grp;
    int b = c >> 10, d = c & 1023;
    float a = -__expf(A_log[d * SDIM + s]);
    float dpar = Dp[d];
    float h = 0.f;
    const float* xb = x + (size_t)b * LSEQ * DDIM + d;
    const float* db = g_delta + (size_t)b * LSEQ * DDIM + d;
    const float* Bb = g_Bm + (size_t)b * LSEQ * SDIM + s;
    const float* Cb = g_Cm + (size_t)b * LSEQ * SDIM + s;
    size_t ybase = (size_t)b * LSEQ * DDIM + d;
#pragma unroll 4
    for (int t = 0; t < LSEQ; t++) {
        float dv = db[(size_t)t * DDIM];
        float xv = xb[(size_t)t * DDIM];
        float Bv = Bb[t * SDIM];
        float Cv = Cb[t * SDIM];
        float barA = __expf(fminf(dv * a, 10.f));
        float barB = fminf(fmaxf(dv * Bv, -10.f), 10.f);
        h = fminf(fmaxf(fmaf(barA, h, barB * xv), -10000.f), 10000.f);
        float p = h * Cv;
        p += __shfl_xor_sync(0xffffffffu, p, 8);
        p += __shfl_xor_sync(0xffffffffu, p, 4);
        p += __shfl_xor_sync(0xffffffffu, p, 2);
        p += __shfl_xor_sync(0xffffffffu, p, 1);
        if (s == 0) {
            float y = p + xv * dpar;
            size_t idx = ybase + (size_t)t * DDIM;
            g_ssm[idx] = y;
            __nv_bfloat16 hh = __float2bfloat16(y);
            g_ssm_h[idx] = hh;
            g_ssm_l[idx] = __float2bfloat16(y - __bfloat162float(hh));
        }
    }
}

// ---------------- router ----------------
__global__ void k_router(const float* __restrict__ Wr) {
    int wid = (blockIdx.x * blockDim.x + threadIdx.x) >> 5;
    int lane = threadIdx.x & 31;
    if (wid >= NTOK) return;
    const float* xr = g_ssm + (size_t)wid * DDIM;
    float l[4] = {0.f, 0.f, 0.f, 0.f};
    for (int k = lane; k < DDIM; k += 32) {
        float xv = xr[k];
        float4 w = *(const float4*)(Wr + (size_t)k * 4);
        l[0] = fmaf(xv, w.x, l[0]);
        l[1] = fmaf(xv, w.y, l[1]);
        l[2] = fmaf(xv, w.z, l[2]);
        l[3] = fmaf(xv, w.w, l[3]);
    }
#pragma unroll
    for (int e = 0; e < 4; e++)
#pragma unroll
        for (int o = 16; o > 0; o >>= 1) l[e] += __shfl_xor_sync(0xffffffffu, l[e], o);
    if (lane == 0) {
        float m = fmaxf(fmaxf(l[0], l[1]), fmaxf(l[2], l[3]));
        float p[4]; float ssum = 0.f;
#pragma unroll
        for (int e = 0; e < 4; e++) { p[e] = __expf(l[e] - m); ssum += p[e]; }
#pragma unroll
        for (int e = 0; e < 4; e++) p[e] /= ssum;
        int e1 = 0; float b1 = p[0];
#pragma unroll
        for (int e = 1; e < 4; e++) if (p[e] > b1) { b1 = p[e]; e1 = e; }
        int e2 = -1; float b2 = -1.f;
#pragma unroll
        for (int e = 0; e < 4; e++) if (e != e1 && p[e] > b2) { b2 = p[e]; e2 = e; }
        float wsum = b1 + b2 + 1e-9f;
        float w1 = b1 / wsum, w2 = b2 / wsum;
        int pos1 = atomicAdd(&g_cnt[e1], 1);
        g_list[e1 * NTOK + pos1] = wid; g_wgt[e1 * NTOK + pos1] = w1;
        int pos2 = atomicAdd(&g_cnt[e2], 1);
        g_list[e2 * NTOK + pos2] = wid; g_wgt[e2 * NTOK + pos2] = w2;
    }
}

// ---------------- final rmsnorm(ssm + moe) ----------------
__global__ void k_final(const float* __restrict__ nw, float* __restrict__ out) {
    int n = blockIdx.x;
    int t = threadIdx.x;
    float v[4]; float ss = 0.f;
#pragma unroll
    for (int i = 0; i < 4; i++) {
        int j = t + i * 256;
        v[i] = g_ssm[(size_t)n * DDIM + j] + g_moe[(size_t)n * DDIM + j];
        ss += v[i] * v[i];
    }
    ss = blockReduceSum(ss);
    float inv = 1.f / sqrtf(ss * (1.f / DDIM) + 1e-6f);
#pragma unroll
    for (int i = 0; i < 4; i++) {
        int j = t + i * 256;
        out[(size_t)n * DDIM + j] = nw[j] * v[i] * inv;
    }
}

// ---------------- launch ----------------
extern "C" void kernel_launch(void* const* d_in, const int* in_sizes, int n_in,
                              void* d_out, int out_size) {
    (void)in_sizes; (void)n_in; (void)out_size;
    const float* x        = (const float*)d_in[0];
    const float* A_log    = (const float*)d_in[1];
    const float* D_param  = (const float*)d_in[2];
    const float* W_delta  = (const float*)d_in[3];
    const float* b_delta  = (const float*)d_in[4];
    const float* W_B      = (const float*)d_in[5];
    const float* W_C      = (const float*)d_in[6];
    const float* W_router = (const float*)d_in[7];
    const float* Wg       = (const float*)d_in[8];
    const float* Wu       = (const float*)d_in[9];
    const float* Wd       = (const float*)d_in[10];
    const float* wn_exp   = (const float*)d_in[11];
    const float* norm_w   = (const float*)d_in[12];
    float* out = (float*)d_out;

    __nv_bfloat16 *xh, *xl, *deh, *del, *gh, *gl, *uh, *ul, *dnh, *dnl;
    cudaGetSymbolAddress((void**)&xh,  g_x_h);
    cudaGetSymbolAddress((void**)&xl,  g_x_l);
    cudaGetSymbolAddress((void**)&deh, g_Wde_h);
    cudaGetSymbolAddress((void**)&del, g_Wde_l);
    cudaGetSymbolAddress((void**)&gh,  g_Wg_h);
    cudaGetSymbolAddress((void**)&gl,  g_Wg_l);
    cudaGetSymbolAddress((void**)&uh,  g_Wu_h);
    cudaGetSymbolAddress((void**)&ul,  g_Wu_l);
    cudaGetSymbolAddress((void**)&dnh, g_Wdn_h);
    cudaGetSymbolAddress((void**)&dnl, g_Wdn_l);

    k_zero<<<1024, 256>>>();
    k_conv<<<1024, 256>>>((const float4*)x,       (uint2*)xh,  (uint2*)xl,  NTOK * DDIM / 4);
    k_conv<<<1024, 256>>>((const float4*)W_delta, (uint2*)deh, (uint2*)del, DDIM * DDIM / 4);
    k_conv<<<2048, 256>>>((const float4*)Wg,      (uint2*)gh,  (uint2*)gl,  NEXP * DDIM * HDIM / 4);
    k_conv<<<2048, 256>>>((const float4*)Wu,      (uint2*)uh,  (uint2*)ul,  NEXP * DDIM * HDIM / 4);
    k_conv<<<2048, 256>>>((const float4*)Wd,      (uint2*)dnh, (uint2*)dnl, NEXP * HDIM * DDIM / 4);

    k_delta<<<dim3(32, 8), 256>>>(b_delta);
    k_bc<<<512, 256>>>(x, W_B, W_C);
    k_scan<<<128, 256>>>(x, A_log, D_param);
    k_router<<<512, 256>>>(W_router);

    k_gate<<<dim3(32, 16, NEXP), 256>>>();
    k_up<<<dim3(32, 16, NEXP), 256>>>();
    k_rmsg<<<dim3(NTOK, NEXP), 256>>>(wn_exp);
    k_down<<<dim3(32, 8, NEXP), 256>>>();

    k_final<<<4096, 256>>>(norm_w, out);
}

// round 15
// speedup vs baseline: 1.6016x; 1.2418x over previous
#include <cuda_runtime.h>
#include <cuda_fp16.h>
#include <math.h>

#define NTOK 4096
#define DDIM 1024
#define SDIM 16
#define NEXP 4
#define HDIM 2048
#define LSEQ 2048

// ---------------- scratch (static device globals; no allocation) ----------------
__device__ float g_delta[NTOK * DDIM];
__device__ float g_Bm[NTOK * SDIM];
__device__ float g_Cm[NTOK * SDIM];
__device__ float g_ssm[NTOK * DDIM];
__device__ float g_moe[NTOK * DDIM];
__device__ float g_G[NEXP * NTOK * HDIM];   // fp32 per-expert hidden
__device__ int   g_cnt[NEXP];
__device__ int   g_list[NEXP * NTOK];
__device__ float g_wgt[NEXP * NTOK];

// fp16 operands: A-side hi only; B-side (weights) hi+lo split
__device__ __align__(16) __half g_x_h[NTOK * DDIM];
__device__ __align__(16) __half g_ssm_h[NTOK * DDIM];
__device__ __align__(16) __half g_G_h[NEXP * NTOK * HDIM];
__device__ __align__(16) __half g_Wde_h[DDIM * DDIM];
__device__ __align__(16) __half g_Wde_l[DDIM * DDIM];
__device__ __align__(16) __half g_Wg_h[NEXP * DDIM * HDIM];
__device__ __align__(16) __half g_Wg_l[NEXP * DDIM * HDIM];
__device__ __align__(16) __half g_Wu_h[NEXP * DDIM * HDIM];
__device__ __align__(16) __half g_Wu_l[NEXP * DDIM * HDIM];
__device__ __align__(16) __half g_Wdn_h[NEXP * HDIM * DDIM];
__device__ __align__(16) __half g_Wdn_l[NEXP * HDIM * DDIM];

// ---------------- helpers ----------------
__device__ __forceinline__ float softplusf(float z) {
    return fmaxf(z, 0.f) + log1pf(__expf(-fabsf(z)));
}
__device__ __forceinline__ float blockReduceSum(float v) {
    __shared__ float sh[9];
    int lane = threadIdx.x & 31, wid = threadIdx.x >> 5;
#pragma unroll
    for (int o = 16; o > 0; o >>= 1) v += __shfl_xor_sync(0xffffffffu, v, o);
    if (lane == 0) sh[wid] = v;
    __syncthreads();
    if (wid == 0) {
        float t = (lane < 8) ? sh[lane] : 0.f;
#pragma unroll
        for (int o = 4; o > 0; o >>= 1) t += __shfl_xor_sync(0xffffffffu, t, o);
        if (lane == 0) sh[8] = t;
    }
    __syncthreads();
    return sh[8];
}
__device__ __forceinline__ unsigned sptr(const void* p) {
    return (unsigned)__cvta_generic_to_shared(p);
}
__device__ __forceinline__ void ldmA(unsigned addr, unsigned& a0, unsigned& a1,
                                     unsigned& a2, unsigned& a3) {
    asm volatile("ldmatrix.sync.aligned.m8n8.x4.shared.b16 {%0,%1,%2,%3}, [%4];"
                 : "=r"(a0), "=r"(a1), "=r"(a2), "=r"(a3) : "r"(addr));
}
__device__ __forceinline__ void ldmB(unsigned addr, unsigned& b0, unsigned& b1) {
    asm volatile("ldmatrix.sync.aligned.m8n8.x2.trans.shared.b16 {%0,%1}, [%2];"
                 : "=r"(b0), "=r"(b1) : "r"(addr));
}
__device__ __forceinline__ void mma16816(float* c, const unsigned* a, unsigned b0, unsigned b1) {
    asm volatile("mma.sync.aligned.m16n8k16.row.col.f32.f16.f16.f32 "
                 "{%0,%1,%2,%3}, {%4,%5,%6,%7}, {%8,%9}, {%0,%1,%2,%3};"
                 : "+f"(c[0]), "+f"(c[1]), "+f"(c[2]), "+f"(c[3])
                 : "r"(a[0]), "r"(a[1]), "r"(a[2]), "r"(a[3]), "r"(b0), "r"(b1));
}
#define CPA(dst, src) \
    asm volatile("cp.async.ca.shared.global [%0], [%1], 16;" :: "r"(sptr(dst)), "l"(src))

// ---------------- zero + convert ----------------
__global__ void k_zero() {
    int i = blockIdx.x * blockDim.x + threadIdx.x;
    int stride = gridDim.x * blockDim.x;
    for (int j = i; j < NTOK * DDIM; j += stride) g_moe[j] = 0.f;
    if (i < NEXP) g_cnt[i] = 0;
}

// fp32 -> fp16 hi only (A-side activations)
__global__ void k_conv1(const float4* __restrict__ src, uint2* __restrict__ h, int n4) {
    int i = blockIdx.x * blockDim.x + threadIdx.x;
    int stride = gridDim.x * blockDim.x;
    for (; i < n4; i += stride) {
        float4 v = src[i];
        __half h0 = __float2half(v.x), h1 = __float2half(v.y);
        __half h2 = __float2half(v.z), h3 = __float2half(v.w);
        uint2 hv;
        hv.x = ((unsigned)__half_as_ushort(h1) << 16) | __half_as_ushort(h0);
        hv.y = ((unsigned)__half_as_ushort(h3) << 16) | __half_as_ushort(h2);
        h[i] = hv;
    }
}

// fp32 -> fp16 hi + lo (B-side weights)
__global__ void k_conv2(const float4* __restrict__ src, uint2* __restrict__ h,
                        uint2* __restrict__ l, int n4) {
    int i = blockIdx.x * blockDim.x + threadIdx.x;
    int stride = gridDim.x * blockDim.x;
    for (; i < n4; i += stride) {
        float4 v = src[i];
        __half h0 = __float2half(v.x), h1 = __float2half(v.y);
        __half h2 = __float2half(v.z), h3 = __float2half(v.w);
        __half l0 = __float2half(v.x - __half2float(h0));
        __half l1 = __float2half(v.y - __half2float(h1));
        __half l2 = __float2half(v.z - __half2float(h2));
        __half l3 = __float2half(v.w - __half2float(h3));
        uint2 hv, lv;
        hv.x = ((unsigned)__half_as_ushort(h1) << 16) | __half_as_ushort(h0);
        hv.y = ((unsigned)__half_as_ushort(h3) << 16) | __half_as_ushort(h2);
        lv.x = ((unsigned)__half_as_ushort(l1) << 16) | __half_as_ushort(l0);
        lv.y = ((unsigned)__half_as_ushort(l3) << 16) | __half_as_ushort(l2);
        h[i] = hv; l[i] = lv;
    }
}

// ============================================================================
// fp16 2-pass split GEMM core. BM=128, BN=128, BK=32, 256 thr (8 warps 2x4),
// warp tile 64x32. Single-buffer smem (~27.6KB).
// D = Ah@Bh + Ah@Bl  (fp32 accumulate; error ~ al*b ~ 2^-12 relative)
// ============================================================================
#define GEMM_SMEM                                            \
    __shared__ __align__(16) unsigned short Ah[128][40];     \
    __shared__ __align__(16) unsigned short Bh[32][136];     \
    __shared__ __align__(16) unsigned short Bl[32][136];

#define GEMM_PRE                                                        \
    int tid = threadIdx.x, lane = tid & 31, wrp = tid >> 5;             \
    int wm = wrp >> 2, wn = wrp & 3;                                    \
    int arow = tid >> 1, akb = (tid & 1) * 16;                          \
    int bkr = tid >> 3, bnc = (tid & 7) * 16;                           \
    float acc[4][4][4] = {};

#define GEMM_LOAD(k0)                                                   \
    {                                                                   \
        CPA(&Ah[arow][akb],     aph + (k0) + akb);                      \
        CPA(&Ah[arow][akb + 8], aph + (k0) + akb + 8);                  \
        const __half* _bh = bph + (size_t)(k0) * NN;                    \
        const __half* _bl = bpl + (size_t)(k0) * NN;                    \
        CPA(&Bh[bkr][bnc],     _bh + bnc);                              \
        CPA(&Bh[bkr][bnc + 8], _bh + bnc + 8);                          \
        CPA(&Bl[bkr][bnc],     _bl + bnc);                              \
        CPA(&Bl[bkr][bnc + 8], _bl + bnc + 8);                          \
        asm volatile("cp.async.commit_group;");                         \
        asm volatile("cp.async.wait_group 0;");                         \
        __syncthreads();                                                \
    }

#define GEMM_COMPUTE                                                          \
    _Pragma("unroll")                                                         \
    for (int ks = 0; ks < 2; ks++) {                                          \
        unsigned ah[4][4], bh[4][2], bl[4][2];                                \
        int acol2 = ks * 16 + (lane >> 4) * 8;                                \
        int marow = wm * 64 + (lane & 15);                                    \
        _Pragma("unroll")                                                     \
        for (int mb = 0; mb < 4; mb++)                                        \
            ldmA(sptr(&Ah[marow + mb * 16][acol2]),                           \
                 ah[mb][0], ah[mb][1], ah[mb][2], ah[mb][3]);                 \
        int bkrow = ks * 16 + (lane & 15);                                    \
        _Pragma("unroll")                                                     \
        for (int nb = 0; nb < 4; nb++) {                                      \
            int nc = wn * 32 + nb * 8;                                        \
            ldmB(sptr(&Bh[bkrow][nc]), bh[nb][0], bh[nb][1]);                 \
            ldmB(sptr(&Bl[bkrow][nc]), bl[nb][0], bl[nb][1]);                 \
        }                                                                     \
        _Pragma("unroll")                                                     \
        for (int mb = 0; mb < 4; mb++)                                        \
            _Pragma("unroll")                                                 \
            for (int nb = 0; nb < 4; nb++) {                                  \
                mma16816(acc[mb][nb], ah[mb], bh[nb][0], bh[nb][1]);          \
                mma16816(acc[mb][nb], ah[mb], bl[nb][0], bl[nb][1]);          \
            }                                                                 \
    }

#define GEMM_MAIN(KTOT)                       \
    for (int k0 = 0; k0 < (KTOT); k0 += 32) { \
        GEMM_LOAD(k0)                         \
        GEMM_COMPUTE                          \
        __syncthreads();                      \
    }

// ---------------- delta GEMM: softplus(x @ W_delta + b) ----------------
__global__ void __launch_bounds__(256) k_delta(const float* __restrict__ bd) {
    GEMM_SMEM
    GEMM_PRE
    const int NN = DDIM;
    int rowBase = blockIdx.x * 128, colBase = blockIdx.y * 128;
    const __half* aph = g_x_h + (size_t)(rowBase + arow) * DDIM;
    const __half* bph = g_Wde_h + (size_t)bkr * NN + colBase;
    const __half* bpl = g_Wde_l + (size_t)bkr * NN + colBase;
    GEMM_MAIN(DDIM)
    int g = lane >> 2, t = lane & 3;
#pragma unroll
    for (int mb = 0; mb < 4; mb++) {
        int r0 = rowBase + wm * 64 + mb * 16 + g;
#pragma unroll
        for (int nb = 0; nb < 4; nb++) {
            int c0 = colBase + wn * 32 + nb * 8 + t * 2;
            float b0 = bd[c0], b1 = bd[c0 + 1];
            g_delta[(size_t)r0 * NN + c0]           = softplusf(acc[mb][nb][0] + b0);
            g_delta[(size_t)r0 * NN + c0 + 1]       = softplusf(acc[mb][nb][1] + b1);
            g_delta[(size_t)(r0 + 8) * NN + c0]     = softplusf(acc[mb][nb][2] + b0);
            g_delta[(size_t)(r0 + 8) * NN + c0 + 1] = softplusf(acc[mb][nb][3] + b1);
        }
    }
}

// ---------------- gate GEMM (gathered, batched experts): G = silu(X@Wg) ----------------
__global__ void __launch_bounds__(256) k_gate() {
    GEMM_SMEM
    GEMM_PRE
    const int NN = HDIM;
    int e = blockIdx.z;
    int cnt = g_cnt[e];
    int rowBase = blockIdx.x * 128;
    if (rowBase >= cnt) return;
    int colBase = blockIdx.y * 128;
    int grow = rowBase + arow;
    int src = (grow < cnt) ? g_list[e * NTOK + grow] : g_list[e * NTOK];
    const __half* aph = g_ssm_h + (size_t)src * DDIM;
    const __half* bph = g_Wg_h + (size_t)e * DDIM * HDIM + (size_t)bkr * NN + colBase;
    const __half* bpl = g_Wg_l + (size_t)e * DDIM * HDIM + (size_t)bkr * NN + colBase;
    GEMM_MAIN(DDIM)
    int g = lane >> 2, t = lane & 3;
    float* Gout = g_G + (size_t)e * NTOK * HDIM;
#pragma unroll
    for (int mb = 0; mb < 4; mb++) {
        int r0 = rowBase + wm * 64 + mb * 16 + g;
#pragma unroll
        for (int nb = 0; nb < 4; nb++) {
            int c0 = colBase + wn * 32 + nb * 8 + t * 2;
            if (r0 < cnt) {
                float v0 = acc[mb][nb][0], v1 = acc[mb][nb][1];
                Gout[(size_t)r0 * NN + c0]     = v0 / (1.f + __expf(-v0));
                Gout[(size_t)r0 * NN + c0 + 1] = v1 / (1.f + __expf(-v1));
            }
            if (r0 + 8 < cnt) {
                float v2 = acc[mb][nb][2], v3 = acc[mb][nb][3];
                Gout[(size_t)(r0 + 8) * NN + c0]     = v2 / (1.f + __expf(-v2));
                Gout[(size_t)(r0 + 8) * NN + c0 + 1] = v3 / (1.f + __expf(-v3));
            }
        }
    }
}

// ---------------- up GEMM (gathered, batched experts): G *= X@Wu ----------------
__global__ void __launch_bounds__(256) k_up() {
    GEMM_SMEM
    GEMM_PRE
    const int NN = HDIM;
    int e = blockIdx.z;
    int cnt = g_cnt[e];
    int rowBase = blockIdx.x * 128;
    if (rowBase >= cnt) return;
    int colBase = blockIdx.y * 128;
    int grow = rowBase + arow;
    int src = (grow < cnt) ? g_list[e * NTOK + grow] : g_list[e * NTOK];
    const __half* aph = g_ssm_h + (size_t)src * DDIM;
    const __half* bph = g_Wu_h + (size_t)e * DDIM * HDIM + (size_t)bkr * NN + colBase;
    const __half* bpl = g_Wu_l + (size_t)e * DDIM * HDIM + (size_t)bkr * NN + colBase;
    GEMM_MAIN(DDIM)
    int g = lane >> 2, t = lane & 3;
    float* Gout = g_G + (size_t)e * NTOK * HDIM;
#pragma unroll
    for (int mb = 0; mb < 4; mb++) {
        int r0 = rowBase + wm * 64 + mb * 16 + g;
#pragma unroll
        for (int nb = 0; nb < 4; nb++) {
            int c0 = colBase + wn * 32 + nb * 8 + t * 2;
            if (r0 < cnt) {
                Gout[(size_t)r0 * NN + c0]     *= acc[mb][nb][0];
                Gout[(size_t)r0 * NN + c0 + 1] *= acc[mb][nb][1];
            }
            if (r0 + 8 < cnt) {
                Gout[(size_t)(r0 + 8) * NN + c0]     *= acc[mb][nb][2];
                Gout[(size_t)(r0 + 8) * NN + c0 + 1] *= acc[mb][nb][3];
            }
        }
    }
}

// ---------------- rmsnorm over expert hidden rows -> fp16 hi ----------------
__global__ void k_rmsg(const float* __restrict__ wn) {
    int e = blockIdx.y;
    int m = blockIdx.x;
    if (m >= g_cnt[e]) return;
    size_t base = ((size_t)e * NTOK + m) * HDIM;
    const float* row = g_G + base;
    const float* w = wn + (size_t)e * HDIM;
    float v[8]; float ss = 0.f;
#pragma unroll
    for (int i = 0; i < 8; i++) {
        v[i] = row[threadIdx.x + i * 256];
        ss += v[i] * v[i];
    }
    ss = blockReduceSum(ss);
    float inv = 1.f / sqrtf(ss * (1.f / HDIM) + 1e-6f);
#pragma unroll
    for (int i = 0; i < 8; i++) {
        int j = threadIdx.x + i * 256;
        g_G_h[base + j] = __float2half(w[j] * v[i] * inv);
    }
}

// ---------------- down GEMM + weighted atomic scatter (batched experts) ----------------
__global__ void __launch_bounds__(256) k_down() {
    GEMM_SMEM
    GEMM_PRE
    const int NN = DDIM;
    int e = blockIdx.z;
    int cnt = g_cnt[e];
    int rowBase = blockIdx.x * 128;
    if (rowBase >= cnt) return;
    int colBase = blockIdx.y * 128;
    int grow = rowBase + arow;
    int ar2 = (grow < cnt) ? grow : (cnt - 1);
    const __half* aph = g_G_h + ((size_t)e * NTOK + ar2) * HDIM;
    const __half* bph = g_Wdn_h + (size_t)e * HDIM * DDIM + (size_t)bkr * NN + colBase;
    const __half* bpl = g_Wdn_l + (size_t)e * HDIM * DDIM + (size_t)bkr * NN + colBase;
    GEMM_MAIN(HDIM)
    int g = lane >> 2, t = lane & 3;
#pragma unroll
    for (int mb = 0; mb < 4; mb++) {
        int r0 = rowBase + wm * 64 + mb * 16 + g;
#pragma unroll
        for (int nb = 0; nb < 4; nb++) {
            int c0 = colBase + wn * 32 + nb * 8 + t * 2;
            if (r0 < cnt) {
                int tok = g_list[e * NTOK + r0];
                float w = g_wgt[e * NTOK + r0];
                atomicAdd(&g_moe[(size_t)tok * NN + c0],     w * acc[mb][nb][0]);
                atomicAdd(&g_moe[(size_t)tok * NN + c0 + 1], w * acc[mb][nb][1]);
            }
            if (r0 + 8 < cnt) {
                int tok = g_list[e * NTOK + r0 + 8];
                float w = g_wgt[e * NTOK + r0 + 8];
                atomicAdd(&g_moe[(size_t)tok * NN + c0],     w * acc[mb][nb][2]);
                atomicAdd(&g_moe[(size_t)tok * NN + c0 + 1], w * acc[mb][nb][3]);
            }
        }
    }
}

// ---------------- Bm / Cm ----------------
__global__ void k_bc(const float* __restrict__ x, const float* __restrict__ WB,
                     const float* __restrict__ WC) {
    int wid = (blockIdx.x * blockDim.x + threadIdx.x) >> 5;
    int lane = threadIdx.x & 31;
    if (wid >= NTOK) return;
    const float* W = (lane < 16) ? WB : WC;
    int col = lane & 15;
    const float* xr = x + (size_t)wid * DDIM;
    float acc = 0.f;
#pragma unroll 8
    for (int k = 0; k < DDIM; k++) acc = fmaf(xr[k], W[k * SDIM + col], acc);
    if (lane < 16) g_Bm[wid * SDIM + col] = acc;
    else           g_Cm[wid * SDIM + col] = acc;
}

// ---------------- selective scan + fp16 epilogue ----------------
__global__ void k_scan(const float* __restrict__ x, const float* __restrict__ A_log,
                       const float* __restrict__ Dp) {
    int tid = threadIdx.x;
    int grp = tid >> 4, s = tid & 15;
    int c = blockIdx.x * 16 + grp;
    int b = c >> 10, d = c & 1023;
    float a = -__expf(A_log[d * SDIM + s]);
    float dpar = Dp[d];
    float h = 0.f;
    const float* xb = x + (size_t)b * LSEQ * DDIM + d;
    const float* db = g_delta + (size_t)b * LSEQ * DDIM + d;
    const float* Bb = g_Bm + (size_t)b * LSEQ * SDIM + s;
    const float* Cb = g_Cm + (size_t)b * LSEQ * SDIM + s;
    size_t ybase = (size_t)b * LSEQ * DDIM + d;
#pragma unroll 4
    for (int t = 0; t < LSEQ; t++) {
        float dv = db[(size_t)t * DDIM];
        float xv = xb[(size_t)t * DDIM];
        float Bv = Bb[t * SDIM];
        float Cv = Cb[t * SDIM];
        float barA = __expf(fminf(dv * a, 10.f));
        float barB = fminf(fmaxf(dv * Bv, -10.f), 10.f);
        h = fminf(fmaxf(fmaf(barA, h, barB * xv), -10000.f), 10000.f);
        float p = h * Cv;
        p += __shfl_xor_sync(0xffffffffu, p, 8);
        p += __shfl_xor_sync(0xffffffffu, p, 4);
        p += __shfl_xor_sync(0xffffffffu, p, 2);
        p += __shfl_xor_sync(0xffffffffu, p, 1);
        if (s == 0) {
            float y = p + xv * dpar;
            size_t idx = ybase + (size_t)t * DDIM;
            g_ssm[idx] = y;
            g_ssm_h[idx] = __float2half(y);
        }
    }
}

// ---------------- router ----------------
__global__ void k_router(const float* __restrict__ Wr) {
    int wid = (blockIdx.x * blockDim.x + threadIdx.x) >> 5;
    int lane = threadIdx.x & 31;
    if (wid >= NTOK) return;
    const float* xr = g_ssm + (size_t)wid * DDIM;
    float l[4] = {0.f, 0.f, 0.f, 0.f};
    for (int k = lane; k < DDIM; k += 32) {
        float xv = xr[k];
        float4 w = *(const float4*)(Wr + (size_t)k * 4);
        l[0] = fmaf(xv, w.x, l[0]);
        l[1] = fmaf(xv, w.y, l[1]);
        l[2] = fmaf(xv, w.z, l[2]);
        l[3] = fmaf(xv, w.w, l[3]);
    }
#pragma unroll
    for (int e = 0; e < 4; e++)
#pragma unroll
        for (int o = 16; o > 0; o >>= 1) l[e] += __shfl_xor_sync(0xffffffffu, l[e], o);
    if (lane == 0) {
        float m = fmaxf(fmaxf(l[0], l[1]), fmaxf(l[2], l[3]));
        float p[4]; float ssum = 0.f;
#pragma unroll
        for (int e = 0; e < 4; e++) { p[e] = __expf(l[e] - m); ssum += p[e]; }
#pragma unroll
        for (int e = 0; e < 4; e++) p[e] /= ssum;
        int e1 = 0; float b1 = p[0];
#pragma unroll
        for (int e = 1; e < 4; e++) if (p[e] > b1) { b1 = p[e]; e1 = e; }
        int e2 = -1; float b2 = -1.f;
#pragma unroll
        for (int e = 0; e < 4; e++) if (e != e1 && p[e] > b2) { b2 = p[e]; e2 = e; }
        float wsum = b1 + b2 + 1e-9f;
        float w1 = b1 / wsum, w2 = b2 / wsum;
        int pos1 = atomicAdd(&g_cnt[e1], 1);
        g_list[e1 * NTOK + pos1] = wid; g_wgt[e1 * NTOK + pos1] = w1;
        int pos2 = atomicAdd(&g_cnt[e2], 1);
        g_list[e2 * NTOK + pos2] = wid; g_wgt[e2 * NTOK + pos2] = w2;
    }
}

// ---------------- final rmsnorm(ssm + moe) ----------------
__global__ void k_final(const float* __restrict__ nw, float* __restrict__ out) {
    int n = blockIdx.x;
    int t = threadIdx.x;
    float v[4]; float ss = 0.f;
#pragma unroll
    for (int i = 0; i < 4; i++) {
        int j = t + i * 256;
        v[i] = g_ssm[(size_t)n * DDIM + j] + g_moe[(size_t)n * DDIM + j];
        ss += v[i] * v[i];
    }
    ss = blockReduceSum(ss);
    float inv = 1.f / sqrtf(ss * (1.f / DDIM) + 1e-6f);
#pragma unroll
    for (int i = 0; i < 4; i++) {
        int j = t + i * 256;
        out[(size_t)n * DDIM + j] = nw[j] * v[i] * inv;
    }
}

// ---------------- launch ----------------
extern "C" void kernel_launch(void* const* d_in, const int* in_sizes, int n_in,
                              void* d_out, int out_size) {
    (void)in_sizes; (void)n_in; (void)out_size;
    const float* x        = (const float*)d_in[0];
    const float* A_log    = (const float*)d_in[1];
    const float* D_param  = (const float*)d_in[2];
    const float* W_delta  = (const float*)d_in[3];
    const float* b_delta  = (const float*)d_in[4];
    const float* W_B      = (const float*)d_in[5];
    const float* W_C      = (const float*)d_in[6];
    const float* W_router = (const float*)d_in[7];
    const float* Wg       = (const float*)d_in[8];
    const float* Wu       = (const float*)d_in[9];
    const float* Wd       = (const float*)d_in[10];
    const float* wn_exp   = (const float*)d_in[11];
    const float* norm_w   = (const float*)d_in[12];
    float* out = (float*)d_out;

    __half *xh, *deh, *del, *gh, *gl, *uh, *ul, *dnh, *dnl;
    cudaGetSymbolAddress((void**)&xh,  g_x_h);
    cudaGetSymbolAddress((void**)&deh, g_Wde_h);
    cudaGetSymbolAddress((void**)&del, g_Wde_l);
    cudaGetSymbolAddress((void**)&gh,  g_Wg_h);
    cudaGetSymbolAddress((void**)&gl,  g_Wg_l);
    cudaGetSymbolAddress((void**)&uh,  g_Wu_h);
    cudaGetSymbolAddress((void**)&ul,  g_Wu_l);
    cudaGetSymbolAddress((void**)&dnh, g_Wdn_h);
    cudaGetSymbolAddress((void**)&dnl, g_Wdn_l);

    k_zero<<<1024, 256>>>();
    k_conv1<<<1024, 256>>>((const float4*)x,      (uint2*)xh, NTOK * DDIM / 4);
    k_conv2<<<1024, 256>>>((const float4*)W_delta, (uint2*)deh, (uint2*)del, DDIM * DDIM / 4);
    k_conv2<<<2048, 256>>>((const float4*)Wg,      (uint2*)gh,  (uint2*)gl,  NEXP * DDIM * HDIM / 4);
    k_conv2<<<2048, 256>>>((const float4*)Wu,      (uint2*)uh,  (uint2*)ul,  NEXP * DDIM * HDIM / 4);
    k_conv2<<<2048, 256>>>((const float4*)Wd,      (uint2*)dnh, (uint2*)dnl, NEXP * HDIM * DDIM / 4);

    k_delta<<<dim3(32, 8), 256>>>(b_delta);
    k_bc<<<512, 256>>>(x, W_B, W_C);
    k_scan<<<128, 256>>>(x, A_log, D_param);
    k_router<<<512, 256>>>(W_router);

    k_gate<<<dim3(32, 16, NEXP), 256>>>();
    k_up<<<dim3(32, 16, NEXP), 256>>>();
    k_rmsg<<<dim3(NTOK, NEXP), 256>>>(wn_exp);
    k_down<<<dim3(32, 8, NEXP), 256>>>();

    k_final<<<4096, 256>>>(norm_w, out);
}